// round 3
// baseline (speedup 1.0000x reference)
#include <cuda_runtime.h>
#include <math.h>
#include <float.h>

#define HIDDEN 5120
#define NH 40
#define HD 128
#define MAXL 2048
#define QL 8
#define CHUNK 256
#define NCHUNK (MAXL / CHUNK)
#define QK_SCALE 0.08838834764831845f  // 1/sqrt(128)
#define C4 (HIDDEN / 4)                // 1280 float4 per row

// packed f32x2 FMA: acc(lo,hi) += a(lo,hi)*b(lo,hi)
#define FMAX2(acc, a, b) \
    asm("fma.rn.f32x2 %0, %1, %2, %0;" : "+l"(acc) : "l"(a), "l"(b))

__device__ __forceinline__ float x2lo(unsigned long long v) {
    return __uint_as_float((unsigned)(v & 0xffffffffu));
}
__device__ __forceinline__ float x2hi(unsigned long long v) {
    return __uint_as_float((unsigned)(v >> 32));
}
__device__ __forceinline__ float x2sum(unsigned long long v) {
    return x2lo(v) + x2hi(v);
}
__device__ __forceinline__ unsigned long long f32dup(float p) {
    unsigned b = __float_as_uint(p);
    return ((unsigned long long)b << 32) | b;
}

// ---------------- device scratch (no allocs allowed) ----------------
__device__ float g_q[NH * QL * HD];                    // [h][q][d], pre-scaled
__device__ float g_k[NH * QL * HD];                    // new K rows  [h][q][d]
__device__ float g_v[NH * QL * HD];                    // new V rows  [h][q][d]
__device__ float g_opart[NH * QL * NCHUNK * HD];       // [h][q][chunk][d]
__device__ float g_m[NH * QL * NCHUNK];                // chunk max
__device__ float g_l[NH * QL * NCHUNK];                // chunk expsum
__device__ float g_ctx[QL * HIDDEN];                   // attention out [q][h*128+d]

// ---------------------------------------------------------------
// GEMV, M=8: Y[q][r] = dot(X[q], W[r]). 8 rows/block, 8 q register tile,
// f32x2 column-pair accumulation (both operand pairs natural from float4).
// W via __ldcg (L2-only) so X stays L1-resident across CTAs.
// mode 0: W_pack -> g_q/g_k/g_v.  mode 1: W_o, X=g_ctx -> Y.
// ---------------------------------------------------------------
__global__ void __launch_bounds__(256) gemv8_kernel(
    const float* __restrict__ Xin, const float* __restrict__ W,
    float* __restrict__ Y, int mode)
{
    __shared__ float sred[8][64];      // 8 warps x (8 rows * 8 q)

    const ulonglong2* __restrict__ X2 =
        reinterpret_cast<const ulonglong2*>((mode == 1) ? g_ctx : Xin);
    const ulonglong2* __restrict__ W2 = reinterpret_cast<const ulonglong2*>(W);

    int tid = threadIdx.x;
    long r0 = (long)blockIdx.x * 8;
    const ulonglong2* __restrict__ Wp = W2 + (size_t)r0 * C4;

    unsigned long long acc[8][8];      // pair over (even,odd) columns
#pragma unroll
    for (int r = 0; r < 8; r++)
#pragma unroll
        for (int q = 0; q < 8; q++) acc[r][q] = 0ull;

#pragma unroll 1
    for (int c4 = tid; c4 < C4; c4 += 256) {
        ulonglong2 wv[8];
#pragma unroll
        for (int r = 0; r < 8; r++)
            wv[r] = __ldcg(Wp + (size_t)r * C4 + c4);
        ulonglong2 xv[8];
#pragma unroll
        for (int q = 0; q < 8; q++)
            xv[q] = __ldg(X2 + q * C4 + c4);
#pragma unroll
        for (int q = 0; q < 8; q++) {
#pragma unroll
            for (int r = 0; r < 8; r++) {
                FMAX2(acc[r][q], wv[r].x, xv[q].x);
                FMAX2(acc[r][q], wv[r].y, xv[q].y);
            }
        }
    }

    // block reduction: lane-sum, warp shuffle, cross-warp via smem
    int lane = tid & 31, warp = tid >> 5;
#pragma unroll
    for (int r = 0; r < 8; r++) {
#pragma unroll
        for (int q = 0; q < 8; q++) {
            float v = x2sum(acc[r][q]);
            v += __shfl_down_sync(0xffffffffu, v, 16);
            v += __shfl_down_sync(0xffffffffu, v, 8);
            v += __shfl_down_sync(0xffffffffu, v, 4);
            v += __shfl_down_sync(0xffffffffu, v, 2);
            v += __shfl_down_sync(0xffffffffu, v, 1);
            if (lane == 0) sred[warp][r * 8 + q] = v;
        }
    }
    __syncthreads();
    if (tid < 64) {
        float v = 0.0f;
#pragma unroll
        for (int w = 0; w < 8; w++) v += sred[w][tid];
        long r = r0 + tid / 8;
        int q = tid % 8;
        if (mode == 0) {
            int sect = (int)(r / HIDDEN);      // 0=q, 1=k, 2=v
            int f = (int)(r % HIDDEN);
            int h = f / HD, d = f % HD;
            int o = (h * QL + q) * HD + d;
            if (sect == 0)      g_q[o] = v * QK_SCALE;
            else if (sect == 1) g_k[o] = v;
            else                g_v[o] = v;
        } else {
            Y[(long)q * HIDDEN + r] = v;
        }
    }
}

// ---------------------------------------------------------------
// Split-KV attention: block = (chunk of 256 keys, head). f32x2 in both
// matmul phases; probs stored pre-duplicated (p,p) in smem for PV phase.
// ---------------------------------------------------------------
__global__ void __launch_bounds__(256) attn_kernel(
    const float* __restrict__ kc, const float* __restrict__ vc,
    const float* __restrict__ mask, const int* __restrict__ ipos)
{
    int chunk = blockIdx.x;
    int h = blockIdx.y;
    int tid = threadIdx.x;
    int warp = tid >> 5, lane = tid & 31;

    __shared__ float qs[QL][HD];                    // 4 KB
    __shared__ float scf[QL][CHUNK];                // 8 KB scores
    __shared__ unsigned long long sc2[QL][CHUNK];   // 16 KB dup probs
    __shared__ float4 red[8][QL][32];               // 32 KB partial O
    __shared__ int pos[QL];
    __shared__ int sel[CHUNK];

    if (tid == 0) {
        bool is64 = (ipos[1] == 0);     // int64 little-endian high word
#pragma unroll
        for (int j = 0; j < QL; j++) pos[j] = is64 ? ipos[2 * j] : ipos[j];
    }
    for (int i = tid; i < QL * HD; i += 256) qs[0][i] = g_q[h * QL * HD + i];
    __syncthreads();

    // ---- scores: one key per thread, f32x2 pairs over d ----
    int key = chunk * CHUNK + tid;
    int s = -1;
#pragma unroll
    for (int j = 0; j < QL; j++) if (pos[j] == key) s = j;
    sel[tid] = s;

    const ulonglong2* kp = reinterpret_cast<const ulonglong2*>(
        (s >= 0) ? &g_k[(h * QL + s) * HD]
                 : &kc[((size_t)h * MAXL + key) * HD]);
    unsigned long long a2[QL];
#pragma unroll
    for (int q = 0; q < QL; q++) a2[q] = 0ull;
#pragma unroll
    for (int c = 0; c < HD / 4; c += 8) {
        ulonglong2 kv[8];
#pragma unroll
        for (int u = 0; u < 8; u++) kv[u] = __ldcg(kp + c + u);
#pragma unroll
        for (int u = 0; u < 8; u++) {
#pragma unroll
            for (int q = 0; q < QL; q++) {
                ulonglong2 qv = *reinterpret_cast<const ulonglong2*>(
                    &qs[q][(c + u) * 4]);
                FMAX2(a2[q], kv[u].x, qv.x);
                FMAX2(a2[q], kv[u].y, qv.y);
            }
        }
    }
#pragma unroll
    for (int q = 0; q < QL; q++) {
        float m = __ldcg(&mask[((size_t)h * MAXL + pos[q]) * MAXL + key]);
        scf[q][tid] = fmaxf(x2sum(a2[q]) + m, -FLT_MAX);
    }
    __syncthreads();

    // ---- softmax stats: warp q handles query q; write dup probs ----
    {
        float m = -FLT_MAX;
#pragma unroll
        for (int i = 0; i < CHUNK / 32; i++) m = fmaxf(m, scf[warp][lane + i * 32]);
#pragma unroll
        for (int o = 16; o > 0; o >>= 1) m = fmaxf(m, __shfl_xor_sync(0xffffffffu, m, o));
        float l = 0.0f;
#pragma unroll
        for (int i = 0; i < CHUNK / 32; i++) {
            float p = __expf(scf[warp][lane + i * 32] - m);
            sc2[warp][lane + i * 32] = f32dup(p);
            l += p;
        }
#pragma unroll
        for (int o = 16; o > 0; o >>= 1) l += __shfl_xor_sync(0xffffffffu, l, o);
        if (lane == 0) {
            g_m[(h * QL + warp) * NCHUNK + chunk] = m;
            g_l[(h * QL + warp) * NCHUNK + chunk] = l;
        }
    }
    __syncthreads();

    // ---- partial O = P^T V. warp w: keys w,w+8,...; lane: d-float4 ----
    unsigned long long acc[QL][2];     // 2 d-pairs per lane
#pragma unroll
    for (int q = 0; q < QL; q++) { acc[q][0] = 0ull; acc[q][1] = 0ull; }

#pragma unroll
    for (int j = 0; j < 32; j += 4) {
        ulonglong2 vv[4];
#pragma unroll
        for (int u = 0; u < 4; u++) {
            int k = warp + 8 * (j + u);
            int sv = sel[k];
            int kk = chunk * CHUNK + k;
            const ulonglong2* vp = reinterpret_cast<const ulonglong2*>(
                (sv >= 0) ? &g_v[(h * QL + sv) * HD]
                          : &vc[((size_t)h * MAXL + kk) * HD]);
            vv[u] = __ldcg(vp + lane);
        }
#pragma unroll
        for (int u = 0; u < 4; u++) {
            int k = warp + 8 * (j + u);
#pragma unroll
            for (int q = 0; q < QL; q++) {
                unsigned long long p2 = sc2[q][k];
                FMAX2(acc[q][0], p2, vv[u].x);
                FMAX2(acc[q][1], p2, vv[u].y);
            }
        }
    }
#pragma unroll
    for (int q = 0; q < QL; q++)
        red[warp][q][lane] = make_float4(x2lo(acc[q][0]), x2hi(acc[q][0]),
                                         x2lo(acc[q][1]), x2hi(acc[q][1]));
    __syncthreads();

    // reduce 8 warps: thread t handles (q, d4) = (t/32, t%32)
    {
        int q = tid >> 5, d4 = tid & 31;
        float4 o = red[0][q][d4];
#pragma unroll
        for (int w = 1; w < 8; w++) {
            float4 v = red[w][q][d4];
            o.x += v.x; o.y += v.y; o.z += v.z; o.w += v.w;
        }
        reinterpret_cast<float4*>(
            &g_opart[((h * QL + q) * NCHUNK + chunk) * HD])[d4] = o;
    }
}

// ---------------------------------------------------------------
// Combine split-KV partials (log-sum-exp merge) -> context [q][h*128+d]
// ---------------------------------------------------------------
__global__ void __launch_bounds__(HD) combine_kernel()
{
    int hq = blockIdx.x;                // h*QL + q
    int d = threadIdx.x;
    float mv[NCHUNK];
    float M = -FLT_MAX;
#pragma unroll
    for (int c = 0; c < NCHUNK; c++) {
        mv[c] = g_m[hq * NCHUNK + c];
        M = fmaxf(M, mv[c]);
    }
    float wf[NCHUNK];
    float denom = 0.0f;
#pragma unroll
    for (int c = 0; c < NCHUNK; c++) {
        wf[c] = __expf(mv[c] - M);
        denom += g_l[hq * NCHUNK + c] * wf[c];
    }
    float o = 0.0f;
#pragma unroll
    for (int c = 0; c < NCHUNK; c++)
        o += wf[c] * g_opart[(hq * NCHUNK + c) * HD + d];
    o /= denom;
    int h = hq / QL, q = hq % QL;
    g_ctx[q * HIDDEN + h * HD + d] = o;
}

// ---------------------------------------------------------------
extern "C" void kernel_launch(void* const* d_in, const int* in_sizes, int n_in,
                              void* d_out, int out_size)
{
    const int*   ipos  = (const int*)  d_in[0];
    const float* hs    = (const float*)d_in[1];
    const float* mask  = (const float*)d_in[2];
    const float* wpack = (const float*)d_in[3];
    const float* wo    = (const float*)d_in[4];
    const float* kc    = (const float*)d_in[5];
    const float* vc    = (const float*)d_in[6];
    float* out = (float*)d_out;

    // 1) fused QKV projection -> g_q/g_k/g_v
    gemv8_kernel<<<(3 * HIDDEN) / 8, 256>>>(hs, wpack, nullptr, 0);

    // 2) split-KV attention partials
    dim3 ag(NCHUNK, NH);
    attn_kernel<<<ag, 256>>>(kc, vc, mask, ipos);

    // 3) merge partials -> context
    combine_kernel<<<NH * QL, HD>>>();

    // 4) output projection -> d_out
    gemv8_kernel<<<HIDDEN / 8, 256>>>(nullptr, wo, out, 1);
}

// round 4
// speedup vs baseline: 1.1929x; 1.1929x over previous
#include <cuda_runtime.h>
#include <math.h>
#include <float.h>

#define HIDDEN 5120
#define NH 40
#define HD 128
#define MAXL 2048
#define QL 8
#define CHUNK 256
#define NCHUNK (MAXL / CHUNK)
#define QK_SCALE 0.08838834764831845f  // 1/sqrt(128)
#define C4 (HIDDEN / 4)                // 1280 float4 per row

// packed f32x2 FMA: acc(lo,hi) += a(lo,hi)*b(lo,hi)
#define FMAX2(acc, a, b) \
    asm("fma.rn.f32x2 %0, %1, %2, %0;" : "+l"(acc) : "l"(a), "l"(b))

__device__ __forceinline__ float x2lo(unsigned long long v) {
    return __uint_as_float((unsigned)(v & 0xffffffffu));
}
__device__ __forceinline__ float x2hi(unsigned long long v) {
    return __uint_as_float((unsigned)(v >> 32));
}
__device__ __forceinline__ float x2sum(unsigned long long v) {
    return x2lo(v) + x2hi(v);
}
__device__ __forceinline__ unsigned long long f32dup(float p) {
    unsigned b = __float_as_uint(p);
    return ((unsigned long long)b << 32) | b;
}

// ---------------- device scratch (no allocs allowed) ----------------
__device__ float g_q[NH * QL * HD];                    // [h][q][d], pre-scaled
__device__ float g_k[NH * QL * HD];                    // new K rows  [h][q][d]
__device__ float g_v[NH * QL * HD];                    // new V rows  [h][q][d]
__device__ float g_opart[NH * QL * NCHUNK * HD];       // [h][q][chunk][d]
__device__ float g_m[NH * QL * NCHUNK];                // chunk max
__device__ float g_l[NH * QL * NCHUNK];                // chunk expsum
__device__ float g_ctx[QL * HIDDEN];                   // attention out [q][h*128+d]

// ---------------------------------------------------------------
// GEMV, M=8: Y[q][r] = dot(X[q], W[r]).
// 4 rows/block, 8 q register tile, f32x2 column-pair accumulation
// (both operand pairs come naturally packed from 16B loads -> no MOVs).
// W via __ldcg (L1-bypass); X via __ldg (L1-resident, persists across
// CTAs within the launch). 2-stage W prefetch for MLP.
// mode 0: W_pack -> g_q/g_k/g_v.  mode 1: W_o, X=g_ctx -> Y.
// ---------------------------------------------------------------
__global__ void __launch_bounds__(256, 2) gemv8_kernel(
    const float* __restrict__ Xin, const float* __restrict__ W,
    float* __restrict__ Y, int mode)
{
    __shared__ float sred[8][32];      // 8 warps x (4 rows * 8 q)

    const ulonglong2* __restrict__ X2 =
        reinterpret_cast<const ulonglong2*>((mode == 1) ? g_ctx : Xin);
    const ulonglong2* __restrict__ W2 = reinterpret_cast<const ulonglong2*>(W);

    int tid = threadIdx.x;
    long r0 = (long)blockIdx.x * 4;
    const ulonglong2* __restrict__ Wp = W2 + (size_t)r0 * C4;

    unsigned long long acc[4][8];      // pair over (even,odd) columns
#pragma unroll
    for (int r = 0; r < 4; r++)
#pragma unroll
        for (int q = 0; q < 8; q++) acc[r][q] = 0ull;

    // software-pipelined over 5 iterations (C4/256 == 5)
    ulonglong2 wv[2][4];
#pragma unroll
    for (int r = 0; r < 4; r++)
        wv[0][r] = __ldcg(Wp + (size_t)r * C4 + tid);

#pragma unroll
    for (int it = 0; it < 5; it++) {
        int cur = it & 1, nxt = cur ^ 1;
        int c4 = tid + it * 256;
        if (it < 4) {
#pragma unroll
            for (int r = 0; r < 4; r++)
                wv[nxt][r] = __ldcg(Wp + (size_t)r * C4 + c4 + 256);
        }
#pragma unroll
        for (int q = 0; q < 8; q++) {
            ulonglong2 xv = __ldg(X2 + q * C4 + c4);
#pragma unroll
            for (int r = 0; r < 4; r++) {
                FMAX2(acc[r][q], wv[cur][r].x, xv.x);
                FMAX2(acc[r][q], wv[cur][r].y, xv.y);
            }
        }
    }

    // block reduction: lane-sum, warp shuffle, cross-warp via smem
    int lane = tid & 31, warp = tid >> 5;
#pragma unroll
    for (int r = 0; r < 4; r++) {
#pragma unroll
        for (int q = 0; q < 8; q++) {
            float v = x2sum(acc[r][q]);
            v += __shfl_down_sync(0xffffffffu, v, 16);
            v += __shfl_down_sync(0xffffffffu, v, 8);
            v += __shfl_down_sync(0xffffffffu, v, 4);
            v += __shfl_down_sync(0xffffffffu, v, 2);
            v += __shfl_down_sync(0xffffffffu, v, 1);
            if (lane == 0) sred[warp][r * 8 + q] = v;
        }
    }
    __syncthreads();
    if (tid < 32) {
        float v = 0.0f;
#pragma unroll
        for (int w = 0; w < 8; w++) v += sred[w][tid];
        long r = r0 + tid / 8;
        int q = tid % 8;
        if (mode == 0) {
            int sect = (int)(r / HIDDEN);      // 0=q, 1=k, 2=v
            int f = (int)(r % HIDDEN);
            int h = f / HD, d = f % HD;
            int o = (h * QL + q) * HD + d;
            if (sect == 0)      g_q[o] = v * QK_SCALE;
            else if (sect == 1) g_k[o] = v;
            else                g_v[o] = v;
        } else {
            Y[(long)q * HIDDEN + r] = v;
        }
    }
}

// ---------------------------------------------------------------
// Split-KV attention: block = (chunk of 256 keys, head). f32x2 in both
// matmul phases; probs stored pre-duplicated (p,p) in smem for PV phase.
// ---------------------------------------------------------------
__global__ void __launch_bounds__(256) attn_kernel(
    const float* __restrict__ kc, const float* __restrict__ vc,
    const float* __restrict__ mask, const int* __restrict__ ipos)
{
    int chunk = blockIdx.x;
    int h = blockIdx.y;
    int tid = threadIdx.x;
    int warp = tid >> 5, lane = tid & 31;

    __shared__ float qs[QL][HD];                    // 4 KB
    __shared__ float scf[QL][CHUNK];                // 8 KB scores
    __shared__ unsigned long long sc2[QL][CHUNK];   // 16 KB dup probs
    __shared__ float4 red[8][QL][32];               // 32 KB partial O
    __shared__ int pos[QL];
    __shared__ int sel[CHUNK];

    if (tid == 0) {
        bool is64 = (ipos[1] == 0);     // int64 little-endian high word
#pragma unroll
        for (int j = 0; j < QL; j++) pos[j] = is64 ? ipos[2 * j] : ipos[j];
    }
    for (int i = tid; i < QL * HD; i += 256) qs[0][i] = g_q[h * QL * HD + i];
    __syncthreads();

    // ---- scores: one key per thread, f32x2 pairs over d ----
    int key = chunk * CHUNK + tid;
    int s = -1;
#pragma unroll
    for (int j = 0; j < QL; j++) if (pos[j] == key) s = j;
    sel[tid] = s;

    const ulonglong2* kp = reinterpret_cast<const ulonglong2*>(
        (s >= 0) ? &g_k[(h * QL + s) * HD]
                 : &kc[((size_t)h * MAXL + key) * HD]);
    unsigned long long a2[QL];
#pragma unroll
    for (int q = 0; q < QL; q++) a2[q] = 0ull;
#pragma unroll
    for (int c = 0; c < HD / 4; c += 8) {
        ulonglong2 kv[8];
#pragma unroll
        for (int u = 0; u < 8; u++) kv[u] = __ldcg(kp + c + u);
#pragma unroll
        for (int u = 0; u < 8; u++) {
#pragma unroll
            for (int q = 0; q < QL; q++) {
                ulonglong2 qv = *reinterpret_cast<const ulonglong2*>(
                    &qs[q][(c + u) * 4]);
                FMAX2(a2[q], kv[u].x, qv.x);
                FMAX2(a2[q], kv[u].y, qv.y);
            }
        }
    }
#pragma unroll
    for (int q = 0; q < QL; q++) {
        float m = __ldcg(&mask[((size_t)h * MAXL + pos[q]) * MAXL + key]);
        scf[q][tid] = fmaxf(x2sum(a2[q]) + m, -FLT_MAX);
    }
    __syncthreads();

    // ---- softmax stats: warp q handles query q; write dup probs ----
    {
        float m = -FLT_MAX;
#pragma unroll
        for (int i = 0; i < CHUNK / 32; i++) m = fmaxf(m, scf[warp][lane + i * 32]);
#pragma unroll
        for (int o = 16; o > 0; o >>= 1) m = fmaxf(m, __shfl_xor_sync(0xffffffffu, m, o));
        float l = 0.0f;
#pragma unroll
        for (int i = 0; i < CHUNK / 32; i++) {
            float p = __expf(scf[warp][lane + i * 32] - m);
            sc2[warp][lane + i * 32] = f32dup(p);
            l += p;
        }
#pragma unroll
        for (int o = 16; o > 0; o >>= 1) l += __shfl_xor_sync(0xffffffffu, l, o);
        if (lane == 0) {
            g_m[(h * QL + warp) * NCHUNK + chunk] = m;
            g_l[(h * QL + warp) * NCHUNK + chunk] = l;
        }
    }
    __syncthreads();

    // ---- partial O = P^T V. warp w: keys w,w+8,...; lane: d-float4 ----
    unsigned long long acc[QL][2];     // 2 d-pairs per lane
#pragma unroll
    for (int q = 0; q < QL; q++) { acc[q][0] = 0ull; acc[q][1] = 0ull; }

#pragma unroll
    for (int j = 0; j < 32; j += 4) {
        ulonglong2 vv[4];
#pragma unroll
        for (int u = 0; u < 4; u++) {
            int k = warp + 8 * (j + u);
            int sv = sel[k];
            int kk = chunk * CHUNK + k;
            const ulonglong2* vp = reinterpret_cast<const ulonglong2*>(
                (sv >= 0) ? &g_v[(h * QL + sv) * HD]
                          : &vc[((size_t)h * MAXL + kk) * HD]);
            vv[u] = __ldcg(vp + lane);
        }
#pragma unroll
        for (int u = 0; u < 4; u++) {
            int k = warp + 8 * (j + u);
#pragma unroll
            for (int q = 0; q < QL; q++) {
                unsigned long long p2 = sc2[q][k];
                FMAX2(acc[q][0], p2, vv[u].x);
                FMAX2(acc[q][1], p2, vv[u].y);
            }
        }
    }
#pragma unroll
    for (int q = 0; q < QL; q++)
        red[warp][q][lane] = make_float4(x2lo(acc[q][0]), x2hi(acc[q][0]),
                                         x2lo(acc[q][1]), x2hi(acc[q][1]));
    __syncthreads();

    // reduce 8 warps: thread t handles (q, d4) = (t/32, t%32)
    {
        int q = tid >> 5, d4 = tid & 31;
        float4 o = red[0][q][d4];
#pragma unroll
        for (int w = 1; w < 8; w++) {
            float4 v = red[w][q][d4];
            o.x += v.x; o.y += v.y; o.z += v.z; o.w += v.w;
        }
        reinterpret_cast<float4*>(
            &g_opart[((h * QL + q) * NCHUNK + chunk) * HD])[d4] = o;
    }
}

// ---------------------------------------------------------------
// Combine split-KV partials (log-sum-exp merge) -> context [q][h*128+d]
// ---------------------------------------------------------------
__global__ void __launch_bounds__(HD) combine_kernel()
{
    int hq = blockIdx.x;                // h*QL + q
    int d = threadIdx.x;
    float mv[NCHUNK];
    float M = -FLT_MAX;
#pragma unroll
    for (int c = 0; c < NCHUNK; c++) {
        mv[c] = g_m[hq * NCHUNK + c];
        M = fmaxf(M, mv[c]);
    }
    float wf[NCHUNK];
    float denom = 0.0f;
#pragma unroll
    for (int c = 0; c < NCHUNK; c++) {
        wf[c] = __expf(mv[c] - M);
        denom += g_l[hq * NCHUNK + c] * wf[c];
    }
    float o = 0.0f;
#pragma unroll
    for (int c = 0; c < NCHUNK; c++)
        o += wf[c] * g_opart[(hq * NCHUNK + c) * HD + d];
    o /= denom;
    int h = hq / QL, q = hq % QL;
    g_ctx[q * HIDDEN + h * HD + d] = o;
}

// ---------------------------------------------------------------
extern "C" void kernel_launch(void* const* d_in, const int* in_sizes, int n_in,
                              void* d_out, int out_size)
{
    const int*   ipos  = (const int*)  d_in[0];
    const float* hs    = (const float*)d_in[1];
    const float* mask  = (const float*)d_in[2];
    const float* wpack = (const float*)d_in[3];
    const float* wo    = (const float*)d_in[4];
    const float* kc    = (const float*)d_in[5];
    const float* vc    = (const float*)d_in[6];
    float* out = (float*)d_out;

    // 1) fused QKV projection -> g_q/g_k/g_v
    gemv8_kernel<<<(3 * HIDDEN) / 4, 256>>>(hs, wpack, nullptr, 0);

    // 2) split-KV attention partials
    dim3 ag(NCHUNK, NH);
    attn_kernel<<<ag, 256>>>(kc, vc, mask, ipos);

    // 3) merge partials -> context
    combine_kernel<<<NH * QL, HD>>>();

    // 4) output projection -> d_out
    gemv8_kernel<<<HIDDEN / 4, 256>>>(nullptr, wo, out, 1);
}